// round 17
// baseline (speedup 1.0000x reference)
#include <cuda_runtime.h>
#include <math.h>

// Problem constants
#define WINDOW 40
#define E 8
#define FDIM 64
#define TDIM 64
#define KERNEL 5
#define IN_CH 144          // F + 10*E
#define LIN_IN 36          // WINDOW + 1 - KERNEL
#define NCOL 320           // WINDOW * E rank columns
#define NMAX 8192

// Scratch (device globals — no allocation allowed)
__device__ float g_cols[(size_t)NCOL * NMAX];   // [col][n] gathered last-window values
__device__ float g_rankT[(size_t)NCOL * NMAX];  // [col][n] rank/N (coalesced writes)
__device__ float g_rank[(size_t)NMAX * NCOL];   // [n][col] rank/N (coalesced reads)
__device__ float g_part[(size_t)NMAX * LIN_IN]; // [n][t] non-rank conv partials

// ---------------------------------------------------------------------------
// Kernel 1: gather x[:, 24+t, 0:8] -> g_cols[(t*8+f)][n]  (proven ~12us)
// ---------------------------------------------------------------------------
__global__ void gather_kernel(const float* __restrict__ x, int N) {
    __shared__ float tile[256][9];   // pad 9 -> conflict-free both phases
    const int t  = blockIdx.y;
    const int n0 = blockIdx.x * 256;
    const int tid = threadIdx.x;
    const int n = n0 + tid;
    if (n < N) {
        const float4* p = (const float4*)(x + (size_t)n * (TDIM * FDIM) + (24 + t) * FDIM);
        float4 a = p[0], b = p[1];
        tile[tid][0] = a.x; tile[tid][1] = a.y; tile[tid][2] = a.z; tile[tid][3] = a.w;
        tile[tid][4] = b.x; tile[tid][5] = b.y; tile[tid][6] = b.z; tile[tid][7] = b.w;
    }
    __syncthreads();
    #pragma unroll
    for (int idx = tid; idx < 8 * 256; idx += 256) {
        int f = idx >> 8, s = idx & 255;
        int nn = n0 + s;
        if (nn < N) g_cols[(size_t)(t * 8 + f) * NMAX + nn] = tile[s][f];
    }
}

// ---------------------------------------------------------------------------
// Kernel 2: exact stable descending rank (R15-proven packed-word design).
// ---------------------------------------------------------------------------
#define RT 512
#define NBIN 32768                 // 15-bit buckets of the ascending key
#define HWORDS (NBIN / 2)          // 16384 u16-pair words
__device__ __forceinline__ int hphys(unsigned int L) {
    return (int)(((L & 31u) << 9) | (L >> 5));   // bijection on [0,16384), scan = stride-512
}
#define OFF_HIST 32768
#define RANK_SMEM (OFF_HIST + HWORDS * 4)        // 98304 B -> 2 blocks/SM

__device__ __forceinline__ unsigned int key_of(float f) {
    unsigned int u = __float_as_uint(f);
    unsigned int mono = u ^ ((u >> 31) ? 0xFFFFFFFFu : 0x80000000u);
    return ~mono;                   // ascending key == descending value
}

__global__ __launch_bounds__(RT) void rank_kernel(int N) {
    extern __shared__ unsigned char sm_raw[];
    unsigned int* packed = (unsigned int*)sm_raw;
    unsigned int* hist   = (unsigned int*)(sm_raw + OFF_HIST);
    __shared__ unsigned int aux2[16];

    const int c    = blockIdx.x;
    const int tid  = threadIdx.x;
    const int lane = tid & 31, wrp = tid >> 5;
    const float* col = &g_cols[(size_t)c * NMAX];

    for (int i = tid; i < HWORDS; i += RT) hist[i] = 0u;
    __syncthreads();

    for (int i = tid; i < N; i += RT) {
        unsigned int k = key_of(col[i]);
        unsigned int b = k >> 17;
        atomicAdd(&hist[hphys(b >> 1)], 1u << ((b & 1) * 16));
    }
    __syncthreads();

    unsigned int tsum = 0;
    #pragma unroll
    for (int w = 0; w < 32; ++w) {
        unsigned int v = hist[w * 512 + tid];
        tsum += (v & 0xFFFFu) + (v >> 16);
    }
    unsigned int v = tsum;
    #pragma unroll
    for (int d = 1; d < 32; d <<= 1) {
        unsigned int t2 = __shfl_up_sync(0xFFFFFFFFu, v, d);
        if (lane >= d) v += t2;
    }
    if (lane == 31) aux2[wrp] = v;
    __syncthreads();
    if (wrp == 0 && lane < 16) {
        unsigned int s = aux2[lane];
        #pragma unroll
        for (int d = 1; d < 16; d <<= 1) {
            unsigned int t2 = __shfl_up_sync(0x0000FFFFu, s, d);
            if (lane >= d) s += t2;
        }
        aux2[lane] = s;
    }
    __syncthreads();
    unsigned int run = v - tsum + (wrp ? aux2[wrp - 1] : 0u);
    #pragma unroll
    for (int w = 0; w < 32; ++w) {
        unsigned int pv = hist[w * 512 + tid];
        unsigned int lo = pv & 0xFFFFu, hi = pv >> 16;
        hist[w * 512 + tid] = run | ((run + lo) << 16);
        run += lo + hi;
    }
    __syncthreads();

    for (int i = tid; i < N; i += RT) {
        unsigned int k = key_of(col[i]);
        unsigned int b = k >> 17;
        unsigned int sh = (b & 1) * 16;
        unsigned int old = atomicAdd(&hist[hphys(b >> 1)], 1u << sh);
        int pos = (old >> sh) & 0xFFFF;
        packed[pos] = ((k & 0x1FFFFu) << 13) | (unsigned int)i;
    }
    __syncthreads();

    const float inv = 1.0f / (float)N;
    float* dst = &g_rankT[(size_t)c * NMAX];
    for (int i = tid; i < N; i += RT) {
        unsigned int k = key_of(col[i]);
        unsigned int b = k >> 17;
        unsigned int we = hist[hphys(b >> 1)];
        int e = (we >> ((b & 1) * 16)) & 0xFFFF;
        int s = 0;
        if (b) {
            unsigned int b1 = b - 1;
            unsigned int ws2 = hist[hphys(b1 >> 1)];
            s = (ws2 >> ((b1 & 1) * 16)) & 0xFFFF;
        }
        const unsigned int pm = ((k & 0x1FFFFu) << 13) | (unsigned int)i;
        int r = s;
        for (int p = s; p < e; ++p)
            r += (packed[p] < pm);
        dst[i] = (float)r * inv;
    }
}

// ---------------------------------------------------------------------------
// Kernel 3: transpose g_rankT[c][n] -> g_rank[n][c]
// ---------------------------------------------------------------------------
__global__ void transpose_kernel(int N) {
    __shared__ float tile[32][33];
    const int c0 = blockIdx.x * 32;
    const int n0 = blockIdx.y * 32;
    const int tx = threadIdx.x, ty = threadIdx.y;   // 32 x 8
    #pragma unroll
    for (int j = ty; j < 32; j += 8) {
        int n = n0 + tx;
        if (n < N) tile[j][tx] = g_rankT[(size_t)(c0 + j) * NMAX + n];
    }
    __syncthreads();
    #pragma unroll
    for (int j = ty; j < 32; j += 8) {
        int n = n0 + j;
        if (n < N) g_rank[(size_t)n * NCOL + c0 + tx] = tile[tx][j];
    }
}

// ---------------------------------------------------------------------------
// Kernel 4 (main1): rank-INDEPENDENT part. Stats + conv over the 32 non-rank
// channel chunks -> g_part[n][36] pre-activation partials. R15-proven body.
// Rank chunks 20,21 (ch 80-87) and 30,31 (ch 120-127) are excluded;
// chunk remap j' = j<20 ? j : (j<28 ? j+2 : j+4).
// ---------------------------------------------------------------------------
__global__ __launch_bounds__(320, 5) void main1_kernel(
    const float* __restrict__ x, const float* __restrict__ conv_w,
    float* __restrict__ part_out, int N)
{
    __shared__ float xe[59 * 8];
    __shared__ float xc[WINDOW * IN_CH];
    __shared__ float ws[IN_CH * KERNEL];
    __shared__ float part2[36 * 33];      // [t][chunk jj], 32 used, stride 33

    const int n   = blockIdx.x;
    const int tid = threadIdx.x;
    const float* xn = x + (size_t)n * (TDIM * FDIM);

    // ---- phase 1: loads ----
    for (int i = tid; i < IN_CH * KERNEL; i += 320) ws[i] = conv_w[127 * IN_CH * KERNEL + i];
    for (int i = tid; i < 59 * 8; i += 320) {
        int r = i >> 3, f = i & 7;
        xe[i] = xn[(5 + r) * FDIM + f];
    }
    {   // raw channels: x[n, 24:64, 0:64] is 2560 contiguous floats
        const float4* src = (const float4*)(xn + 24 * FDIM);
        for (int q = tid; q < 640; q += 320) {
            float4 v = src[q];
            int l = q * 4;
            int t = l >> 6, i = l & 63;
            *(float4*)&xc[t * IN_CH + i] = v;
        }
    }
    __syncthreads();

    // ---- phase 2: sliding-window stats (thread = one (t,f) pair) ----
    {
        const int t = tid >> 3, f = tid & 7;
        float* row = &xc[t * IN_CH];
        float s = 0.f, s2 = 0.f, mx = -1e30f, mn = 1e30f;
        #pragma unroll
        for (int j = 0; j < 5; ++j) {
            float v = xe[(15 + t + j) * 8 + f];
            s += v; s2 = fmaf(v, v, s2);
            mx = fmaxf(mx, v); mn = fminf(mn, v);
        }
        row[64 + f] = s * 0.2f;
        row[72 + f] = sqrtf(fmaxf((s2 - s * s * 0.2f) * 0.25f, 0.f));
        row[88 + f] = mx;
        row[96 + f] = mn;
        s = 0.f; s2 = 0.f; mx = -1e30f; mn = 1e30f;
        #pragma unroll
        for (int j = 0; j < 20; ++j) {
            float v = xe[(t + j) * 8 + f];
            s += v; s2 = fmaf(v, v, s2);
            mx = fmaxf(mx, v); mn = fminf(mn, v);
        }
        row[104 + f] = s * 0.05f;
        row[112 + f] = sqrtf(fmaxf((s2 - s * s * 0.05f) * (1.0f / 19.0f), 0.f));
        row[128 + f] = mx;
        row[136 + f] = mn;
        // rank channels 80-87 / 120-127 left unwritten — excluded from conv
    }
    __syncthreads();

    // ---- phase 3: conv over 32 non-rank chunks; 128 threads x 9 outputs ----
    if (tid < 128) {
        const int q = tid >> 5, jj = tid & 31;                  // q: 4 groups of 9 t's
        const int cj = (jj < 20) ? jj : ((jj < 28) ? jj + 2 : jj + 4);
        float4 w4[KERNEL];
        #pragma unroll
        for (int k = 0; k < KERNEL; ++k) {
            w4[k].x = ws[(4 * cj + 0) * KERNEL + k];
            w4[k].y = ws[(4 * cj + 1) * KERNEL + k];
            w4[k].z = ws[(4 * cj + 2) * KERNEL + k];
            w4[k].w = ws[(4 * cj + 3) * KERNEL + k];
        }
        float acc[9];
        #pragma unroll
        for (int a = 0; a < 9; ++a) acc[a] = 0.f;
        const float4* xc4 = (const float4*)xc;
        const int r0 = 9 * q;
        #pragma unroll
        for (int rr = 0; rr < 13; ++rr) {
            float4 vv = xc4[(r0 + rr) * 36 + cj];
            #pragma unroll
            for (int k = 0; k < KERNEL; ++k) {
                const int tt = rr - k;
                if (tt >= 0 && tt <= 8) {
                    acc[tt] = fmaf(w4[k].x, vv.x, acc[tt]);
                    acc[tt] = fmaf(w4[k].y, vv.y, acc[tt]);
                    acc[tt] = fmaf(w4[k].z, vv.z, acc[tt]);
                    acc[tt] = fmaf(w4[k].w, vv.w, acc[tt]);
                }
            }
        }
        #pragma unroll
        for (int a = 0; a < 9; ++a) part2[(r0 + a) * 33 + jj] = acc[a];
    }
    __syncthreads();

    if (tid < LIN_IN) {
        float s = 0.f;
        #pragma unroll
        for (int j2 = 0; j2 < 32; ++j2) s += part2[tid * 33 + j2];
        part_out[(size_t)n * LIN_IN + tid] = s;   // pre-activation, no bias yet
    }
}

// ---------------------------------------------------------------------------
// Kernel 5 (main2): join. rank conv (weights of ch 80+f and 120+f folded) +
// non-rank partial + bias -> leaky -> dot lin_w -> out. 8 samples / block.
// ---------------------------------------------------------------------------
__global__ __launch_bounds__(256) void main2_kernel(
    const float* __restrict__ conv_w, const float* __restrict__ conv_b,
    const float* __restrict__ lin_w, const float* __restrict__ lin_b,
    const float* __restrict__ part_in, float* __restrict__ out, int N)
{
    __shared__ float wr[40];             // [f*5+k] folded rank weights
    __shared__ float rk[8][8 * 41];      // [sample][f*41 + tt]
    const int tid = threadIdx.x;
    const int s = tid >> 5, lane = tid & 31;
    const int n = blockIdx.x * 8 + s;

    if (tid < 40) {
        int f = tid / 5, k = tid - 5 * f;
        wr[tid] = conv_w[127 * IN_CH * KERNEL + (80 + f) * KERNEL + k]
                + conv_w[127 * IN_CH * KERNEL + (120 + f) * KERNEL + k];
    }
    if (n < N) {
        const float* rp = g_rank + (size_t)n * NCOL;
        #pragma unroll
        for (int r = 0; r < 10; ++r) {
            int i = lane + 32 * r;              // 0..319, coalesced
            float v = __ldg(rp + i);
            int f = i & 7, tt = i >> 3;
            rk[s][f * 41 + tt] = v;
        }
    }
    __syncthreads();

    if (n < N) {
        const float cb = __ldg(&conv_b[127]);
        float acc = 0.f;
        #pragma unroll
        for (int u = 0; u < 2; ++u) {
            int t = lane + 32 * u;
            if (t < LIN_IN) {
                float c = 0.f;
                #pragma unroll
                for (int f = 0; f < 8; ++f)
                    #pragma unroll
                    for (int k = 0; k < 5; ++k)
                        c = fmaf(wr[f * 5 + k], rk[s][f * 41 + t + k], c);
                float sum = __ldg(&part_in[(size_t)n * LIN_IN + t]) + c + cb;
                sum = (sum >= 0.f) ? sum : 0.01f * sum;     // leaky ALPHA=0.01
                acc = fmaf(sum, __ldg(&lin_w[t]), acc);
            }
        }
        #pragma unroll
        for (int d = 16; d > 0; d >>= 1)
            acc += __shfl_down_sync(0xFFFFFFFFu, acc, d);
        if (lane == 0) out[n] = acc + __ldg(&lin_b[0]);
    }
}

// ---------------------------------------------------------------------------
// Launch: fork rank-chain (stream s1) alongside main1 (legacy stream), join
// with an event, then main2. Graph capture records this as a DAG.
// ---------------------------------------------------------------------------
extern "C" void kernel_launch(void* const* d_in, const int* in_sizes, int n_in,
                              void* d_out, int out_size) {
    const float* x      = (const float*)d_in[0];
    const float* conv_w = (const float*)d_in[1];
    const float* conv_b = (const float*)d_in[2];
    const float* lin_w  = (const float*)d_in[3];
    const float* lin_b  = (const float*)d_in[4];
    float* out = (float*)d_out;
    const int N = in_sizes[0] / (TDIM * FDIM);   // 8000

    cudaFuncSetAttribute(rank_kernel, cudaFuncAttributeMaxDynamicSharedMemorySize, RANK_SMEM);

    float* g_part_p = nullptr;
    cudaGetSymbolAddress((void**)&g_part_p, g_part);

    cudaStream_t s1;
    cudaStreamCreateWithFlags(&s1, cudaStreamNonBlocking);
    cudaEvent_t eFork, eJoin;
    cudaEventCreateWithFlags(&eFork, cudaEventDisableTiming);
    cudaEventCreateWithFlags(&eJoin, cudaEventDisableTiming);

    // fork
    cudaEventRecord(eFork, 0);
    cudaStreamWaitEvent(s1, eFork, 0);

    // branch B (stream s1): gather -> rank -> transpose
    dim3 gg((N + 255) / 256, WINDOW);
    gather_kernel<<<gg, 256, 0, s1>>>(x, N);
    rank_kernel<<<NCOL, RT, RANK_SMEM, s1>>>(N);
    dim3 tb(32, 8);
    dim3 tg(NCOL / 32, (N + 31) / 32);
    transpose_kernel<<<tg, tb, 0, s1>>>(N);

    // branch A (legacy stream): rank-independent main part
    main1_kernel<<<N, 320>>>(x, conv_w, g_part_p, N);

    // join
    cudaEventRecord(eJoin, s1);
    cudaStreamWaitEvent(0, eJoin, 0);
    main2_kernel<<<(N + 7) / 8, 256>>>(conv_w, conv_b, lin_w, lin_b, g_part_p, out, N);

    cudaEventDestroy(eFork);
    cudaEventDestroy(eJoin);
    cudaStreamDestroy(s1);
}